// round 8
// baseline (speedup 1.0000x reference)
#include <cuda_runtime.h>

// GaussianAgg: soft z-buffer aggregation via perturbed argmax.
// Shapes: zbuf/prob/mask [B,H,W,K=32] f32; noise [S=16,B,H,W,33]; out [B,H,W,33].
// ~345 MB HBM traffic, one thread per pixel, noise + output staged through smem
// to avoid stride-132 L1tex wavefront blowup (32 wf/LDG -> data-optimal).

#define GA_NSAMP 16
#define GA_K     32
#define GA_C     33           // K + background channel
#define GA_GAMMA 0.04f
#define GA_EPS   1e-10f
#define GA_TPB   128          // pixels per CTA

__global__ __launch_bounds__(GA_TPB) void gaussian_agg_kernel(
    const float* __restrict__ zbuf,
    const float* __restrict__ zfar,
    const float* __restrict__ znear,
    const float* __restrict__ prob,
    const float* __restrict__ mask,
    const float* __restrict__ noise,
    float* __restrict__ out,
    int npix)
{
    __shared__ __align__(16) float sbuf[GA_TPB * GA_C];   // 16,896 B

    const int t    = threadIdx.x;
    const int base = blockIdx.x * GA_TPB;
    const int p    = base + t;
    const bool active = (p < npix);
    const bool full   = (base + GA_TPB <= npix);          // uniform per CTA

    const float zf = zfar[0];
    const float zn = znear[0];
    const float inv_range = 1.0f / (zf - zn);

    // ---- zmap: gamma*log(1e-12+prob) + z_inv - max(z_inv, EPS-floored) ----
    float zmap[GA_C];
    if (active) {
        const float4* zb4 = reinterpret_cast<const float4*>(zbuf + (size_t)p * GA_K);
        const float4* mk4 = reinterpret_cast<const float4*>(mask + (size_t)p * GA_K);
        float zmax = GA_EPS;
        #pragma unroll
        for (int i = 0; i < GA_K / 4; i++) {
            float4 z = zb4[i];
            float4 m = mk4[i];
            float a0 = (zf - z.x) * inv_range * m.x;
            float a1 = (zf - z.y) * inv_range * m.y;
            float a2 = (zf - z.z) * inv_range * m.z;
            float a3 = (zf - z.w) * inv_range * m.w;
            zmap[4*i + 0] = a0;
            zmap[4*i + 1] = a1;
            zmap[4*i + 2] = a2;
            zmap[4*i + 3] = a3;
            zmax = fmaxf(zmax, fmaxf(fmaxf(a0, a1), fmaxf(a2, a3)));
        }
        const float4* pr4 = reinterpret_cast<const float4*>(prob + (size_t)p * GA_K);
        #pragma unroll
        for (int i = 0; i < GA_K / 4; i++) {
            float4 q = pr4[i];
            zmap[4*i + 0] = GA_GAMMA * logf(1e-12f + q.x) + zmap[4*i + 0] - zmax;
            zmap[4*i + 1] = GA_GAMMA * logf(1e-12f + q.y) + zmap[4*i + 1] - zmax;
            zmap[4*i + 2] = GA_GAMMA * logf(1e-12f + q.z) + zmap[4*i + 2] - zmax;
            zmap[4*i + 3] = GA_GAMMA * logf(1e-12f + q.w) + zmap[4*i + 3] - zmax;
        }
        zmap[GA_K] = GA_EPS - zmax;
    }

    // ---- Per-sample perturbed argmax, noise staged through smem ----
    const size_t samp_stride = (size_t)npix * GA_C;
    const size_t chunk_off   = (size_t)base * GA_C;
    const int    chunk_elems = full ? (GA_TPB * GA_C)
                                    : ((npix - base > 0 ? npix - base : 0) * GA_C);

    int idx[GA_NSAMP];
    #pragma unroll 1
    for (int s = 0; s < GA_NSAMP; s++) {
        __syncthreads();   // previous-iteration smem reads done before overwrite
        const float* src = noise + (size_t)s * samp_stride + chunk_off;
        if (full) {
            // 16,896 B contiguous chunk, 16B-aligned (base*33*4 % 16 == 0 since base%4==0)
            const float4* s4 = reinterpret_cast<const float4*>(src);
            float4*       d4 = reinterpret_cast<float4*>(sbuf);
            for (int i = t; i < GA_TPB * GA_C / 4; i += GA_TPB) d4[i] = s4[i];
        } else {
            for (int i = t; i < chunk_elems; i += GA_TPB) sbuf[i] = src[i];
        }
        __syncthreads();

        if (active) {
            // word-stride 33 across lanes -> bank (lane + c) mod 32: conflict-free
            const float* ns = sbuf + t * GA_C;
            float best = fmaf(GA_GAMMA, ns[0], zmap[0]);
            int bi = 0;
            #pragma unroll
            for (int c = 1; c < GA_C; c++) {
                float v = fmaf(GA_GAMMA, ns[c], zmap[c]);
                if (v > best) { best = v; bi = c; }   // strict >: first-max tie-break
            }
            idx[s] = bi;
        }
    }

    // ---- Mean of one-hots, staged through smem for coalesced stores ----
    __syncthreads();
    if (active) {
        float* row = sbuf + t * GA_C;
        #pragma unroll
        for (int c = 0; c < GA_C; c++) {
            int cnt = 0;
            #pragma unroll
            for (int s = 0; s < GA_NSAMP; s++) cnt += (idx[s] == c);
            row[c] = (float)cnt * (1.0f / (float)GA_NSAMP);
        }
    }
    __syncthreads();

    float* dst = out + chunk_off;
    if (full) {
        const float4* s4 = reinterpret_cast<const float4*>(sbuf);
        float4*       d4 = reinterpret_cast<float4*>(dst);
        for (int i = t; i < GA_TPB * GA_C / 4; i += GA_TPB) d4[i] = s4[i];
    } else {
        for (int i = t; i < chunk_elems; i += GA_TPB) dst[i] = sbuf[i];
    }
}

extern "C" void kernel_launch(void* const* d_in, const int* in_sizes, int n_in,
                              void* d_out, int out_size)
{
    const float* zbuf  = (const float*)d_in[0];
    const float* zfar  = (const float*)d_in[1];
    const float* znear = (const float*)d_in[2];
    const float* prob  = (const float*)d_in[3];
    const float* mask  = (const float*)d_in[4];
    const float* noise = (const float*)d_in[5];
    float* out = (float*)d_out;

    int npix = in_sizes[0] / GA_K;   // B*H*W = 131072

    int blocks = (npix + GA_TPB - 1) / GA_TPB;
    gaussian_agg_kernel<<<blocks, GA_TPB>>>(zbuf, zfar, znear, prob, mask, noise,
                                            out, npix);
}

// round 10
// speedup vs baseline: 1.1458x; 1.1458x over previous
#include <cuda_runtime.h>
#include <cstdint>

// GaussianAgg: soft z-buffer aggregation via perturbed argmax.
// Shapes: zbuf/prob/mask [B,H,W,K=32] f32; noise [S=16,B,H,W,33]; out [B,H,W,33].
// ~345 MB HBM traffic (noise = 277 MB). One thread per pixel.
// R8 -> R9: double-buffered cp.async noise prefetch (continuous DRAM stream,
// loads overlap argmax compute) + 4-way split argmax chain (shorter dep tail).

#define GA_NSAMP 16
#define GA_K     32
#define GA_C     33            // K + background channel
#define GA_GAMMA 0.04f
#define GA_EPS   1e-10f
#define GA_TPB   128           // pixels per CTA

#define CHUNK_FLOATS (GA_TPB * GA_C)        // 4224 floats = 16896 B
#define CHUNK_F4     (CHUNK_FLOATS / 4)     // 1056

__device__ __forceinline__ void cp_async16(uint32_t saddr, const void* gptr) {
    asm volatile("cp.async.ca.shared.global [%0], [%1], 16;\n"
                 :: "r"(saddr), "l"(gptr) : "memory");
}

__global__ __launch_bounds__(GA_TPB) void gaussian_agg_kernel(
    const float* __restrict__ zbuf,
    const float* __restrict__ zfar,
    const float* __restrict__ znear,
    const float* __restrict__ prob,
    const float* __restrict__ mask,
    const float* __restrict__ noise,
    float* __restrict__ out,
    int npix)
{
    __shared__ __align__(16) float sbuf[2 * CHUNK_FLOATS];   // 33,792 B

    const int t    = threadIdx.x;
    const int base = blockIdx.x * GA_TPB;
    const int p    = base + t;
    const bool active = (p < npix);
    const bool full   = (base + GA_TPB <= npix);             // uniform per CTA

    const size_t samp_stride = (size_t)npix * GA_C;
    const size_t chunk_off   = (size_t)base * GA_C;
    const float* nsrc        = noise + chunk_off;
    const uint32_t sb = (uint32_t)__cvta_generic_to_shared(sbuf);

    // ---- Kick off sample-0 noise prefetch BEFORE zmap compute (overlap) ----
    if (full) {
        #pragma unroll
        for (int i = 0; i < (CHUNK_F4 + GA_TPB - 1) / GA_TPB; i++) {
            int e = t + i * GA_TPB;
            if (e < CHUNK_F4) cp_async16(sb + e * 16, nsrc + e * 4);
        }
        asm volatile("cp.async.commit_group;\n" ::: "memory");
    }

    const float zf = zfar[0];
    const float zn = znear[0];
    const float inv_range = 1.0f / (zf - zn);

    // ---- zmap: gamma*log(1e-12+prob) + z_inv - max(z_inv, EPS-floored) ----
    float zmap[GA_C];
    if (active) {
        const float4* zb4 = reinterpret_cast<const float4*>(zbuf + (size_t)p * GA_K);
        const float4* mk4 = reinterpret_cast<const float4*>(mask + (size_t)p * GA_K);
        float zmax = GA_EPS;
        #pragma unroll
        for (int i = 0; i < GA_K / 4; i++) {
            float4 z = zb4[i];
            float4 m = mk4[i];
            float a0 = (zf - z.x) * inv_range * m.x;
            float a1 = (zf - z.y) * inv_range * m.y;
            float a2 = (zf - z.z) * inv_range * m.z;
            float a3 = (zf - z.w) * inv_range * m.w;
            zmap[4*i + 0] = a0;
            zmap[4*i + 1] = a1;
            zmap[4*i + 2] = a2;
            zmap[4*i + 3] = a3;
            zmax = fmaxf(zmax, fmaxf(fmaxf(a0, a1), fmaxf(a2, a3)));
        }
        const float4* pr4 = reinterpret_cast<const float4*>(prob + (size_t)p * GA_K);
        #pragma unroll
        for (int i = 0; i < GA_K / 4; i++) {
            float4 q = pr4[i];
            zmap[4*i + 0] = GA_GAMMA * logf(1e-12f + q.x) + zmap[4*i + 0] - zmax;
            zmap[4*i + 1] = GA_GAMMA * logf(1e-12f + q.y) + zmap[4*i + 1] - zmax;
            zmap[4*i + 2] = GA_GAMMA * logf(1e-12f + q.z) + zmap[4*i + 2] - zmax;
            zmap[4*i + 3] = GA_GAMMA * logf(1e-12f + q.w) + zmap[4*i + 3] - zmax;
        }
        zmap[GA_K] = GA_EPS - zmax;
    }

    // ---- Per-sample perturbed argmax, double-buffered cp.async staging ----
    int idx[GA_NSAMP];
    #pragma unroll 1
    for (int s = 0; s < GA_NSAMP; s++) {
        const int cur = s & 1;

        if (full) {
            // Issue next sample's prefetch into the other buffer first.
            // Its previous reader (sample s-1) finished before the end-of-iter
            // __syncthreads() of the last iteration.
            if (s + 1 < GA_NSAMP) {
                const float* src = nsrc + (size_t)(s + 1) * samp_stride;
                const uint32_t dst = sb + ((s + 1) & 1) * (CHUNK_FLOATS * 4);
                #pragma unroll
                for (int i = 0; i < (CHUNK_F4 + GA_TPB - 1) / GA_TPB; i++) {
                    int e = t + i * GA_TPB;
                    if (e < CHUNK_F4) cp_async16(dst + e * 16, src + e * 4);
                }
                asm volatile("cp.async.commit_group;\n" ::: "memory");
                asm volatile("cp.async.wait_group 1;\n" ::: "memory");  // sample s ready
            } else {
                asm volatile("cp.async.wait_group 0;\n" ::: "memory");
            }
            __syncthreads();   // cross-thread visibility of staged data
        } else {
            // Tail CTA (not hit for npix % 128 == 0): synchronous staging.
            __syncthreads();
            const float* src = nsrc + (size_t)s * samp_stride;
            int elems = (npix - base > 0 ? npix - base : 0) * GA_C;
            for (int i = t; i < elems; i += GA_TPB) sbuf[cur * CHUNK_FLOATS + i] = src[i];
            __syncthreads();
        }

        if (active) {
            // smem row: word-stride 33 across lanes -> bank (lane+c) mod 32, conflict-free.
            const float* ns = sbuf + cur * CHUNK_FLOATS + t * GA_C;
            // 4 independent chains over contiguous ranges; earlier-chain-wins merge
            // preserves exact first-max (strict >) tie-break semantics.
            float b0 = fmaf(GA_GAMMA, ns[0], zmap[0]);  int i0 = 0;
            #pragma unroll
            for (int c = 1; c <= 8; c++) {
                float v = fmaf(GA_GAMMA, ns[c], zmap[c]);
                if (v > b0) { b0 = v; i0 = c; }
            }
            float b1 = fmaf(GA_GAMMA, ns[9], zmap[9]);  int i1 = 9;
            #pragma unroll
            for (int c = 10; c <= 16; c++) {
                float v = fmaf(GA_GAMMA, ns[c], zmap[c]);
                if (v > b1) { b1 = v; i1 = c; }
            }
            float b2 = fmaf(GA_GAMMA, ns[17], zmap[17]); int i2 = 17;
            #pragma unroll
            for (int c = 18; c <= 24; c++) {
                float v = fmaf(GA_GAMMA, ns[c], zmap[c]);
                if (v > b2) { b2 = v; i2 = c; }
            }
            float b3 = fmaf(GA_GAMMA, ns[25], zmap[25]); int i3 = 25;
            #pragma unroll
            for (int c = 26; c <= 32; c++) {
                float v = fmaf(GA_GAMMA, ns[c], zmap[c]);
                if (v > b3) { b3 = v; i3 = c; }
            }
            if (b1 > b0) { b0 = b1; i0 = i1; }
            if (b2 > b0) { b0 = b2; i0 = i2; }
            if (b3 > b0) { b0 = b3; i0 = i3; }
            idx[s] = i0;
        }
        __syncthreads();   // reads done before this buffer is prefetch-overwritten
    }

    // ---- Mean of one-hots, staged through smem for coalesced stores ----
    if (active) {
        float* row = sbuf + t * GA_C;
        #pragma unroll
        for (int c = 0; c < GA_C; c++) {
            int cnt = 0;
            #pragma unroll
            for (int s = 0; s < GA_NSAMP; s++) cnt += (idx[s] == c);
            row[c] = (float)cnt * (1.0f / (float)GA_NSAMP);
        }
    }
    __syncthreads();

    float* dst = out + chunk_off;
    if (full) {
        const float4* s4 = reinterpret_cast<const float4*>(sbuf);
        float4*       d4 = reinterpret_cast<float4*>(dst);
        #pragma unroll
        for (int i = 0; i < (CHUNK_F4 + GA_TPB - 1) / GA_TPB; i++) {
            int e = t + i * GA_TPB;
            if (e < CHUNK_F4) d4[e] = s4[e];
        }
    } else {
        int elems = (npix - base > 0 ? npix - base : 0) * GA_C;
        for (int i = t; i < elems; i += GA_TPB) dst[i] = sbuf[i];
    }
}

extern "C" void kernel_launch(void* const* d_in, const int* in_sizes, int n_in,
                              void* d_out, int out_size)
{
    const float* zbuf  = (const float*)d_in[0];
    const float* zfar  = (const float*)d_in[1];
    const float* znear = (const float*)d_in[2];
    const float* prob  = (const float*)d_in[3];
    const float* mask  = (const float*)d_in[4];
    const float* noise = (const float*)d_in[5];
    float* out = (float*)d_out;

    int npix = in_sizes[0] / GA_K;   // B*H*W = 131072

    int blocks = (npix + GA_TPB - 1) / GA_TPB;
    gaussian_agg_kernel<<<blocks, GA_TPB>>>(zbuf, zfar, znear, prob, mask, noise,
                                            out, npix);
}